// round 13
// baseline (speedup 1.0000x reference)
#include <cuda_runtime.h>
#include <cstdint>

#define B_ 32
#define A_ 8400
#define NC_ 80
#define K_ 1024
#define G_ 32
#define NSUP_ 16
#define MAXDET_ 300
#define CLCAP_ 56

// ---------------- scratch (device globals; no allocation) ----------------
__device__ float  g_conf[B_*A_];
__device__ float4 g_box [B_*A_];
__device__ int    g_cls [B_*A_];

__device__ float  g_tk_conf[B_*K_];
__device__ float4 g_tk_box [B_*K_];
__device__ float  g_tk_sarea[B_*K_];
__device__ int    g_tk_cls [B_*K_];

__device__ __forceinline__ float sel4f(float4 v, int s) {
    float r = v.x;
    r = (s == 1) ? v.y : r;
    r = (s == 2) ? v.z : r;
    r = (s == 3) ? v.w : r;
    return r;
}

// ---------------- K1: decode, 4 threads per anchor-quad (20 classes each) ----------------
__global__ void __launch_bounds__(256, 6) k_decode(const float* __restrict__ preds) {
    const int APQ = A_ / 4;  // 2100
    int gtid = blockIdx.x * blockDim.x + threadIdx.x;   // 268800 threads exactly
    int group = gtid >> 2, sub = gtid & 3;
    int b  = group / APQ;
    int a4 = (group - b * APQ) * 4;
    const float* p = preds + (size_t)b * 84 * A_ + a4;

    // all 4 threads of a group read the same box rows (warp-coalesced broadcast)
    float4 cx = *(const float4*)(p);
    float4 cy = *(const float4*)(p + A_);
    float4 w  = *(const float4*)(p + 2 * A_);
    float4 h  = *(const float4*)(p + 3 * A_);

    float b0 = -1.f, b1 = -1.f, b2 = -1.f, b3 = -1.f;
    int   c0i = 0, c1i = 0, c2i = 0, c3i = 0;
    int cbase = sub * 20;
    const float* ps = p + (size_t)(4 + cbase) * A_;
    #pragma unroll
    for (int q = 0; q < 20; q++) {
        float4 v = *(const float4*)(ps + (size_t)q * A_);
        int c = cbase + q;
        if (v.x > b0) { b0 = v.x; c0i = c; }
        if (v.y > b1) { b1 = v.y; c1i = c; }
        if (v.z > b2) { b2 = v.z; c2i = c; }
        if (v.w > b3) { b3 = v.w; c3i = c; }
    }

    // merge partial (max, first-argmax) across the 4 sub-threads.
    // tie: lower class index wins (matches jnp.argmax first-occurrence).
    #pragma unroll
    for (int o = 1; o <= 2; o <<= 1) {
        float ob0 = __shfl_xor_sync(0xFFFFFFFFu, b0, o);
        int   oc0 = __shfl_xor_sync(0xFFFFFFFFu, c0i, o);
        if (ob0 > b0 || (ob0 == b0 && oc0 < c0i)) { b0 = ob0; c0i = oc0; }
        float ob1 = __shfl_xor_sync(0xFFFFFFFFu, b1, o);
        int   oc1 = __shfl_xor_sync(0xFFFFFFFFu, c1i, o);
        if (ob1 > b1 || (ob1 == b1 && oc1 < c1i)) { b1 = ob1; c1i = oc1; }
        float ob2 = __shfl_xor_sync(0xFFFFFFFFu, b2, o);
        int   oc2 = __shfl_xor_sync(0xFFFFFFFFu, c2i, o);
        if (ob2 > b2 || (ob2 == b2 && oc2 < c2i)) { b2 = ob2; c2i = oc2; }
        float ob3 = __shfl_xor_sync(0xFFFFFFFFu, b3, o);
        int   oc3 = __shfl_xor_sync(0xFFFFFFFFu, c3i, o);
        if (ob3 > b3 || (ob3 == b3 && oc3 < c3i)) { b3 = ob3; c3i = oc3; }
    }

    // thread `sub` writes anchor a4+sub (fully coalesced stores)
    float bs = b0;
    bs = (sub == 1) ? b1 : bs;
    bs = (sub == 2) ? b2 : bs;
    bs = (sub == 3) ? b3 : bs;
    int bcv = c0i;
    bcv = (sub == 1) ? c1i : bcv;
    bcv = (sub == 2) ? c2i : bcv;
    bcv = (sub == 3) ? c3i : bcv;

    float cxs = sel4f(cx, sub), cys = sel4f(cy, sub);
    float ws  = sel4f(w,  sub), hs  = sel4f(h,  sub);
    float conf = bs > 0.25f ? bs : 0.0f;
    float hw = ws * 0.5f, hh = hs * 0.5f;
    int base = b * A_ + a4 + sub;
    g_conf[base] = conf;
    g_box [base] = make_float4(cxs - hw, cys - hh, cxs + hw, cys + hh);
    g_cls [base] = bcv;
}

// ---------------- K2: exact top-K (2-pass radix select + hybrid bitonic) ----------------
__global__ void __launch_bounds__(1024) k_topk() {
    int b = blockIdx.x, tid = threadIdx.x, lane = tid & 31;
    __shared__ unsigned int hist[256];
    __shared__ unsigned int s_prefix, s_need;
    __shared__ int s_cnt;
    __shared__ unsigned long long cand[2048];

    const float* confp = g_conf + b * A_;
    unsigned int cb[9];
    #pragma unroll
    for (int q = 0; q < 9; q++) {
        int a = tid + q * 1024;
        cb[q] = (a < A_) ? __float_as_uint(confp[a]) : 0u;
    }

    unsigned prefix = 0, himask = 0, need = K_;
    #pragma unroll
    for (int pass = 0; pass < 2; pass++) {
        int shift = 24 - pass * 8;
        if (tid < 256) hist[tid] = 0;
        __syncthreads();
        #pragma unroll
        for (int q = 0; q < 9; q++) {
            int a = tid + q * 1024;
            bool ok = (a < A_) && ((cb[q] & himask) == prefix);
            if (ok) {
                unsigned bin = (cb[q] >> shift) & 255u;
                unsigned mmask = __match_any_sync(__activemask(), bin);
                int leader = __ffs(mmask) - 1;
                if ((int)(threadIdx.x & 31) == leader)
                    atomicAdd(&hist[bin], (unsigned)__popc(mmask));
            }
        }
        __syncthreads();
        if (tid == 0) {
            unsigned cum = 0; int sel = 0;
            for (int by = 255; by >= 0; by--) {
                unsigned c2 = hist[by];
                if (cum + c2 >= need) { sel = by; break; }
                cum += c2;
            }
            s_prefix = prefix | ((unsigned)sel << shift);
            s_need = need - cum;
        }
        __syncthreads();
        prefix = s_prefix; need = s_need; himask |= 0xFFu << shift;
        __syncthreads();
    }
    unsigned T = prefix;  // 16-bit prefix threshold (low 16 bits zero)

    if (tid == 0) s_cnt = 0;
    __syncthreads();
    #pragma unroll
    for (int q = 0; q < 9; q++) {
        int a = tid + q * 1024;
        bool sel = (a < A_) && ((cb[q] & 0xFFFF0000u) > T);
        unsigned msel = __ballot_sync(0xFFFFFFFFu, sel);
        int rank = __popc(msel & ((1u << lane) - 1));
        int basep = 0;
        if (lane == 0 && msel) basep = atomicAdd(&s_cnt, __popc(msel));
        basep = __shfl_sync(0xFFFFFFFFu, basep, 0);
        if (sel) {
            int pp = basep + rank;
            if (pp < 2048)
                cand[pp] = ((unsigned long long)cb[q] << 32) | (unsigned)(A_ - 1 - a);
        }
    }
    __syncthreads();
    #pragma unroll
    for (int q = 0; q < 9; q++) {
        int a = tid + q * 1024;
        bool sel = (a < A_) && ((cb[q] & 0xFFFF0000u) == T);
        unsigned msel = __ballot_sync(0xFFFFFFFFu, sel);
        int rank = __popc(msel & ((1u << lane) - 1));
        int basep = 0;
        if (lane == 0 && msel) basep = atomicAdd(&s_cnt, __popc(msel));
        basep = __shfl_sync(0xFFFFFFFFu, basep, 0);
        if (sel) {
            int pp = basep + rank;
            if (pp < 2048)
                cand[pp] = ((unsigned long long)cb[q] << 32) | (unsigned)(A_ - 1 - a);
        }
    }
    __syncthreads();
    int total = min(s_cnt, 2048);
    for (int t = total + tid; t < 2048; t += 1024) cand[t] = 0ull;
    __syncthreads();

    // hybrid bitonic sort, descending, unique keys
    unsigned long long vA = cand[tid], vB = cand[tid + 1024];
    #pragma unroll
    for (int k = 2; k <= 32; k <<= 1) {
        bool descA = ((tid & k) == 0);
        #pragma unroll
        for (int j = k >> 1; j > 0; j >>= 1) {
            bool up = ((tid & j) == 0);
            bool takeMax = (up == descA);
            unsigned long long oA = __shfl_xor_sync(0xFFFFFFFFu, vA, j);
            vA = takeMax ? (vA > oA ? vA : oA) : (vA < oA ? vA : oA);
            unsigned long long oB = __shfl_xor_sync(0xFFFFFFFFu, vB, j);
            vB = takeMax ? (vB > oB ? vB : oB) : (vB < oB ? vB : oB);
        }
    }
    cand[tid] = vA; cand[tid + 1024] = vB;

    #pragma unroll
    for (int k = 64; k <= 2048; k <<= 1) {
        for (int j = k >> 1; j >= 32; j >>= 1) {
            __syncthreads();
            #pragma unroll
            for (int tt = 0; tt < 2; tt++) {
                int t = tid + tt * 1024;
                int ixj = t ^ j;
                if (ixj > t) {
                    unsigned long long x = cand[t], y = cand[ixj];
                    bool desc = ((t & k) == 0);
                    if (desc ? (x < y) : (x > y)) { cand[t] = y; cand[ixj] = x; }
                }
            }
        }
        __syncthreads();
        vA = cand[tid]; vB = cand[tid + 1024];
        bool descA = ((tid & k) == 0);
        bool descB = (((tid + 1024) & k) == 0);
        #pragma unroll
        for (int j = 16; j > 0; j >>= 1) {
            bool up = ((tid & j) == 0);
            unsigned long long oA = __shfl_xor_sync(0xFFFFFFFFu, vA, j);
            vA = ((up == descA)) ? (vA > oA ? vA : oA) : (vA < oA ? vA : oA);
            unsigned long long oB = __shfl_xor_sync(0xFFFFFFFFu, vB, j);
            vB = ((up == descB)) ? (vB > oB ? vB : oB) : (vB < oB ? vB : oB);
        }
        cand[tid] = vA; cand[tid + 1024] = vB;
    }
    __syncthreads();

    {
        unsigned long long key = cand[tid];
        unsigned vbits = (unsigned)(key >> 32);
        int a = A_ - 1 - (int)(key & 0xFFFFFFFFull);
        int gi = b * A_ + a;
        float4 bx = g_box[gi];
        int cl = g_cls[gi];
        float sh = (float)cl * 7680.0f;
        float4 sb = make_float4(bx.x + sh, bx.y + sh, bx.z + sh, bx.w + sh);
        int oi = b * K_ + tid;
        g_tk_conf[oi]  = __uint_as_float(vbits);
        g_tk_box [oi]  = bx;
        g_tk_sarea[oi] = __fmul_rn(sb.z - sb.x, sb.w - sb.y);
        g_tk_cls [oi]  = cl;
    }
}

// ---------------- K3: fused on-the-fly NMS mask + sparse resolve + matching ----------------
__global__ void __launch_bounds__(1024) k_scan_match(
        const float* __restrict__ gt_boxes, const int* __restrict__ gt_cls,
        const void* __restrict__ gt_mask, const int* __restrict__ cat_to_super,
        float* __restrict__ out) {
    int b = blockIdx.x, tid = threadIdx.x, lane = tid & 31, wid = tid >> 5;
    __shared__ float4 sbx[K_];                 // unshifted boxes
    __shared__ float  sconf[K_];
    __shared__ float  sar[K_];                 // shifted-box areas
    __shared__ unsigned char scl[K_];
    __shared__ unsigned long long cmask[NC_ * 16];
    __shared__ unsigned long long keepw[16], validw[16];
    __shared__ unsigned long long colw[64];
    __shared__ unsigned int swords[32], pwords[32];
    __shared__ unsigned int vb[32];
    __shared__ int s_mode, s_done, s_budget;
    __shared__ float4 sgt[G_];
    __shared__ int sgc[G_], sgm[G_];
    __shared__ unsigned long long gkey[G_];
    __shared__ int ccnt[NC_];
    __shared__ unsigned short clist[NC_ * CLCAP_];
    __shared__ int scat[NC_], ssup[NSUP_];

    int oi = b * K_ + tid;
    float4 mybox = g_tk_box[oi];
    float  myconf = g_tk_conf[oi];
    int    mycls = g_tk_cls[oi];
    sbx[tid] = mybox; sconf[tid] = myconf;
    sar[tid] = g_tk_sarea[oi];
    scl[tid] = (unsigned char)mycls;

    if (tid == 0) { s_mode = 0; s_done = 0; s_budget = MAXDET_; }
    if (tid < 16) keepw[tid] = 0ull;
    if (tid < NC_) { ccnt[tid] = 0; scat[tid] = 0; }
    if (tid < NSUP_) ssup[tid] = 0;
    for (int t = tid; t < NC_ * 16; t += 1024) cmask[t] = 0ull;
    __syncthreads();
    atomicOr(&cmask[mycls * 16 + (tid >> 6)], 1ull << (tid & 63));

    // sniff gt_mask dtype from its first 1024 bytes (total elems = 32*32 = 1024)
    {
        const unsigned char* mu = (const unsigned char*)gt_mask;
        unsigned char v = mu[tid];
        if (v == 0x3F) atomicOr(&s_mode, 2);
        else if (v && (tid & 3)) atomicOr(&s_mode, 1);
    }
    unsigned bal = __ballot_sync(0xFFFFFFFFu, myconf > 0.0f);
    if (lane == 0) vb[wid] = bal;
    __syncthreads();

    if (tid < 16)
        validw[tid] = (unsigned long long)vb[2 * tid] | ((unsigned long long)vb[2 * tid + 1] << 32);
    int mode = s_mode;
    if (tid < G_) {
        const float4* gb4 = (const float4*)gt_boxes;
        sgt[tid] = gb4[b * G_ + tid];
        sgc[tid] = gt_cls[b * G_ + tid];
        int m;
        if (mode >= 2)      m = (((const float*)gt_mask)[b * G_ + tid] != 0.0f);
        else if (mode == 1) m = (((const unsigned char*)gt_mask)[b * G_ + tid] != 0);
        else                m = (((const int*)gt_mask)[b * G_ + tid] != 0);
        sgm[tid] = m;
    }
    __syncthreads();

    // greedy NMS: masks computed on the fly vs kept same-class columns,
    // sparse serial resolve, MAX_DET cap fused (early exit at 300 kept).
    {
        int r = tid >> 4, w = tid & 15;   // warp wid covers rows 2*wid, 2*wid+1
        for (int c = 0; c < 16; c++) {
            int i = c * 64 + r;
            int ci = scl[i];
            float shv = (float)ci * 7680.0f;
            float4 bi = sbx[i];
            float bix = bi.x + shv, biy = bi.y + shv;
            float biz = bi.z + shv, biw = bi.w + shv;
            float ai = sar[i];
            bool s = false;
            unsigned long long word = 0ull;
            if (w < c) {
                // suppressed by any KEPT same-class column in chunk w?
                unsigned long long m = cmask[ci * 16 + w] & keepw[w];
                int j0 = w * 64;
                while (m) {
                    int t2 = __ffsll(m) - 1; m &= m - 1;
                    float4 bj = sbx[j0 + t2];
                    float jx = bj.x + shv, jy = bj.y + shv;
                    float jz = bj.z + shv, jw2 = bj.w + shv;
                    float lx = fmaxf(bix, jx), ly = fmaxf(biy, jy);
                    float rx = fminf(biz, jz), ry = fminf(biw, jw2);
                    float ww = fmaxf(rx - lx, 0.0f), hh = fmaxf(ry - ly, 0.0f);
                    float inter = __fmul_rn(ww, hh);
                    float den = ai + sar[j0 + t2];
                    den = den - inter;
                    den = den + 1e-9f;
                    float q = inter / den;
                    if (q > 0.45f) { s = true; break; }
                }
            } else if (w == c) {
                // diagonal word: IoU bits vs same-class columns of own chunk
                unsigned long long m = cmask[ci * 16 + c];
                int j0 = c * 64;
                while (m) {
                    int t2 = __ffsll(m) - 1; m &= m - 1;
                    float4 bj = sbx[j0 + t2];
                    float jx = bj.x + shv, jy = bj.y + shv;
                    float jz = bj.z + shv, jw2 = bj.w + shv;
                    float lx = fmaxf(bix, jx), ly = fmaxf(biy, jy);
                    float rx = fminf(biz, jz), ry = fminf(biw, jw2);
                    float ww = fmaxf(rx - lx, 0.0f), hh = fmaxf(ry - ly, 0.0f);
                    float inter = __fmul_rn(ww, hh);
                    float den = ai + sar[j0 + t2];
                    den = den - inter;
                    den = den + 1e-9f;
                    float q = inter / den;
                    if (q > 0.45f) word |= (1ull << t2);
                }
                colw[r] = word;
            }
            unsigned long long below_r = (r == 0) ? 0ull : ((1ull << r) - 1ull);
            bool probbit = (w == c) && ((word & below_r) != 0ull);
            unsigned sb2 = __ballot_sync(0xFFFFFFFFu, s);
            unsigned pb2 = __ballot_sync(0xFFFFFFFFu, probbit);
            if (lane == 0) { swords[wid] = sb2; pwords[wid] = pb2; }
            __syncthreads();
            if (tid == 0) {
                unsigned long long sup = 0ull, prob = 0ull;
                #pragma unroll
                for (int q2 = 0; q2 < 32; q2++) {
                    unsigned bs_ = swords[q2], bp_ = pwords[q2];
                    if (bs_ & 0xFFFFu)      sup  |= 1ull << (2 * q2);
                    if (bs_ & 0xFFFF0000u)  sup  |= 1ull << (2 * q2 + 1);
                    if (bp_ & 0xFFFFu)      prob |= 1ull << (2 * q2);
                    if (bp_ & 0xFFFF0000u)  prob |= 1ull << (2 * q2 + 1);
                }
                unsigned long long base = validw[c] & ~sup;
                unsigned long long kw = base & ~prob;      // independent rows
                unsigned long long m = base & prob;        // serial fixup rows
                while (m) {
                    int r2 = __ffsll(m) - 1; m &= m - 1;
                    unsigned long long bel = (r2 == 0) ? 0ull : ((1ull << r2) - 1ull);
                    if (!(kw & colw[r2] & bel)) kw |= 1ull << r2;
                }
                int budget = s_budget;
                int pc = __popcll(kw);
                if (pc > budget) {
                    int rm = pc - budget;
                    for (int t3 = 0; t3 < rm; t3++)
                        kw &= ~(0x8000000000000000ull >> __clzll(kw));
                    pc = budget;
                }
                keepw[c] = kw;
                s_budget = budget - pc;
                if (budget == pc) s_done = 1;
            }
            __syncthreads();
            if (s_done) break;   // all later keep bits zeroed by cumsum<=300 cap
        }
    }

    bool kbit = ((keepw[tid >> 6] >> (tid & 63)) & 1ull) != 0;
    bool pv = kbit && (myconf > 0.5f);
    unsigned pb = __ballot_sync(0xFFFFFFFFu, pv);
    if (lane == 0) vb[wid] = pb;

    // compact matching candidates (pv preds) into per-class lists
    if (pv) {
        int p = atomicAdd(&ccnt[mycls], 1);
        if (p < CLCAP_) clist[mycls * CLCAP_ + p] = (unsigned short)tid;
    }
    // per-category / per-super GT counts
    if (tid < G_) {
        int c3 = sgc[tid];
        atomicAdd(&scat[c3], sgm[tid]);
        atomicAdd(&ssup[cat_to_super[c3]], sgm[tid]);
    }
    __syncthreads();

    // warp g handles gt g: only same-class pv preds are eligible
    {
        int g = wid;
        float4 gb = sgt[g];
        int gc = sgc[g];
        float ga = __fmul_rn(gb.z - gb.x, gb.w - gb.y);
        int n = min(ccnt[gc], CLCAP_);
        unsigned long long key = 0ull;
        for (int t = lane; t < n; t += 32) {
            int idx = clist[gc * CLCAP_ + t];
            float4 pbx = sbx[idx];
            float ap = __fmul_rn(pbx.z - pbx.x, pbx.w - pbx.y);
            float lx = fmaxf(pbx.x, gb.x), ly = fmaxf(pbx.y, gb.y);
            float rx = fminf(pbx.z, gb.z), ry = fminf(pbx.w, gb.w);
            float ww = fmaxf(rx - lx, 0.0f), hh = fmaxf(ry - ly, 0.0f);
            float inter = __fmul_rn(ww, hh);
            float den = ap + ga;
            den = den - inter;
            den = den + 1e-9f;
            float val = inter / den;
            unsigned fb = __float_as_uint(val);
            unsigned ord = fb ^ ((fb & 0x80000000u) ? 0xFFFFFFFFu : 0x80000000u);
            unsigned long long k2 = ((unsigned long long)ord << 32) | (unsigned)(K_ - 1 - idx);
            if (k2 > key) key = k2;
        }
        #pragma unroll
        for (int o = 16; o > 0; o >>= 1) {
            unsigned long long other = __shfl_xor_sync(0xFFFFFFFFu, key, o);
            if (other > key) key = other;
        }
        if (lane == 0) gkey[g] = key;
    }
    __syncthreads();

    if (tid == 0) {
        int n_pred = 0;
        for (int w2 = 0; w2 < 32; w2++) n_pred += __popc(vb[w2]);
        float sum_iou = 0.f, sum_conf = 0.f;
        int n_hit = 0, n_gt = 0;
        for (int g = 0; g < G_; g++) {
            int m = sgm[g];
            n_gt += m;
            unsigned long long key = gkey[g];
            unsigned ord = (unsigned)(key >> 32);
            unsigned fb = ord ^ ((ord & 0x80000000u) ? 0x80000000u : 0xFFFFFFFFu);
            float biou = __uint_as_float(fb);
            if (m && (biou > 0.6f)) {
                int idx = K_ - 1 - (int)(key & 0xFFFFFFFFull);
                n_hit++;
                sum_iou += biou;
                sum_conf += sconf[idx];
            }
        }
        float r0, r1, r2v, r3, r4;
        if (n_gt == 0) {
            if (n_pred == 0) { r0 = 1.f; r1 = 1.f; r2v = -1.f; r3 = -1.f; r4 = 1.f; }
            else             { r0 = 0.f; r1 = 1.f; r2v = -2.f; r3 = -2.f; r4 = 0.f; }
        } else {
            float fh = (float)n_hit;
            r0 = sum_iou / fmaxf(fh, 1.0f);
            r1 = (n_hit > 0) ? (sum_conf / fmaxf(fh, 1.0f)) : 1.0f;
            int bc2 = 0, bv = scat[0];
            for (int c3 = 1; c3 < NC_; c3++) if (scat[c3] > bv) { bv = scat[c3]; bc2 = c3; }
            int bs2 = 0, bvs = ssup[0];
            for (int s3 = 1; s3 < NSUP_; s3++) if (ssup[s3] > bvs) { bvs = ssup[s3]; bs2 = s3; }
            r2v = (float)bc2; r3 = (float)bs2;
            r4 = fh / fmaxf((float)n_gt, 1.0f);
        }
        out[b * 5 + 0] = r0; out[b * 5 + 1] = r1; out[b * 5 + 2] = r2v;
        out[b * 5 + 3] = r3; out[b * 5 + 4] = r4;
    }
}

// ---------------- launch ----------------
extern "C" void kernel_launch(void* const* d_in, const int* in_sizes, int n_in,
                              void* d_out, int out_size) {
    const float* preds = (const float*)d_in[0];
    const float* gtb   = (const float*)d_in[1];
    const int*   gtc   = (const int*)d_in[2];
    const void*  gtm   = d_in[3];
    const int*   c2s   = (const int*)d_in[4];
    float* out = (float*)d_out;

    int n1 = (B_ * A_ + 255) / 256;   // 4 threads per anchor-quad -> B*A threads total
    k_decode<<<n1, 256>>>(preds);
    k_topk<<<B_, 1024>>>();
    k_scan_match<<<B_, 1024>>>(gtb, gtc, gtm, c2s, out);
}

// round 14
// speedup vs baseline: 1.1728x; 1.1728x over previous
#include <cuda_runtime.h>
#include <cstdint>

#define B_ 32
#define A_ 8400
#define NC_ 80
#define K_ 1024
#define G_ 32
#define NSUP_ 16
#define MAXDET_ 300
#define CLCAP_ 56

// ---------------- scratch (device globals; no allocation) ----------------
__device__ float  g_conf[B_*A_];
__device__ float4 g_box [B_*A_];
__device__ int    g_cls [B_*A_];

__device__ float  g_tk_conf[B_*K_];
__device__ float4 g_tk_box [B_*K_];
__device__ float  g_tk_sarea[B_*K_];
__device__ int    g_tk_cls [B_*K_];

// ---------------- K1: decode + per-anchor class max/argmax (R9 layout, deeper MLP) ----------------
__global__ void __launch_bounds__(256) k_decode(const float* __restrict__ preds) {
    const int APQ = A_ / 4;  // 2100
    int idx = blockIdx.x * blockDim.x + threadIdx.x;
    if (idx >= B_ * APQ) return;
    int b  = idx / APQ;
    int a4 = (idx - b * APQ) * 4;
    const float* p = preds + (size_t)b * 84 * A_ + a4;

    float4 cx = *(const float4*)(p);
    float4 cy = *(const float4*)(p + A_);
    float4 w  = *(const float4*)(p + 2 * A_);
    float4 h  = *(const float4*)(p + 3 * A_);

    float best0 = -1.f, best1 = -1.f, best2 = -1.f, best3 = -1.f;
    int   bc0 = 0, bc1 = 0, bc2 = 0, bc3 = 0;
    // 20-deep load batches: ~2.5x more loads in flight per warp than unroll 8.
    #pragma unroll 20
    for (int c = 0; c < NC_; c++) {
        float4 v = *(const float4*)(p + (size_t)(4 + c) * A_);
        if (v.x > best0) { best0 = v.x; bc0 = c; }
        if (v.y > best1) { best1 = v.y; bc1 = c; }
        if (v.z > best2) { best2 = v.z; bc2 = c; }
        if (v.w > best3) { best3 = v.w; bc3 = c; }
    }
    int base = b * A_ + a4;
    float bests[4] = {best0, best1, best2, best3};
    int   bcs[4]   = {bc0, bc1, bc2, bc3};
    float cxs[4] = {cx.x, cx.y, cx.z, cx.w};
    float cys[4] = {cy.x, cy.y, cy.z, cy.w};
    float ws[4]  = {w.x,  w.y,  w.z,  w.w};
    float hs[4]  = {h.x,  h.y,  h.z,  h.w};
    #pragma unroll
    for (int t = 0; t < 4; t++) {
        float conf = bests[t] > 0.25f ? bests[t] : 0.0f;
        float hw = ws[t] * 0.5f, hh = hs[t] * 0.5f;
        g_conf[base + t] = conf;
        g_box [base + t] = make_float4(cxs[t] - hw, cys[t] - hh, cxs[t] + hw, cys[t] + hh);
        g_cls [base + t] = bcs[t];
    }
}

// ---------------- K2: exact top-K (2-pass radix select + hybrid bitonic) ----------------
__global__ void __launch_bounds__(1024) k_topk() {
    int b = blockIdx.x, tid = threadIdx.x, lane = tid & 31;
    __shared__ unsigned int hist[256];
    __shared__ unsigned int s_prefix, s_need;
    __shared__ int s_cnt;
    __shared__ unsigned long long cand[2048];

    const float* confp = g_conf + b * A_;
    unsigned int cb[9];
    #pragma unroll
    for (int q = 0; q < 9; q++) {
        int a = tid + q * 1024;
        cb[q] = (a < A_) ? __float_as_uint(confp[a]) : 0u;
    }

    unsigned prefix = 0, himask = 0, need = K_;
    #pragma unroll
    for (int pass = 0; pass < 2; pass++) {
        int shift = 24 - pass * 8;
        if (tid < 256) hist[tid] = 0;
        __syncthreads();
        #pragma unroll
        for (int q = 0; q < 9; q++) {
            int a = tid + q * 1024;
            bool ok = (a < A_) && ((cb[q] & himask) == prefix);
            if (ok) {
                unsigned bin = (cb[q] >> shift) & 255u;
                unsigned mmask = __match_any_sync(__activemask(), bin);
                int leader = __ffs(mmask) - 1;
                if ((int)(threadIdx.x & 31) == leader)
                    atomicAdd(&hist[bin], (unsigned)__popc(mmask));
            }
        }
        __syncthreads();
        if (tid == 0) {
            unsigned cum = 0; int sel = 0;
            for (int by = 255; by >= 0; by--) {
                unsigned c2 = hist[by];
                if (cum + c2 >= need) { sel = by; break; }
                cum += c2;
            }
            s_prefix = prefix | ((unsigned)sel << shift);
            s_need = need - cum;
        }
        __syncthreads();
        prefix = s_prefix; need = s_need; himask |= 0xFFu << shift;
        __syncthreads();
    }
    unsigned T = prefix;  // 16-bit prefix threshold (low 16 bits zero)

    if (tid == 0) s_cnt = 0;
    __syncthreads();
    #pragma unroll
    for (int q = 0; q < 9; q++) {
        int a = tid + q * 1024;
        bool sel = (a < A_) && ((cb[q] & 0xFFFF0000u) > T);
        unsigned msel = __ballot_sync(0xFFFFFFFFu, sel);
        int rank = __popc(msel & ((1u << lane) - 1));
        int basep = 0;
        if (lane == 0 && msel) basep = atomicAdd(&s_cnt, __popc(msel));
        basep = __shfl_sync(0xFFFFFFFFu, basep, 0);
        if (sel) {
            int pp = basep + rank;
            if (pp < 2048)
                cand[pp] = ((unsigned long long)cb[q] << 32) | (unsigned)(A_ - 1 - a);
        }
    }
    __syncthreads();
    #pragma unroll
    for (int q = 0; q < 9; q++) {
        int a = tid + q * 1024;
        bool sel = (a < A_) && ((cb[q] & 0xFFFF0000u) == T);
        unsigned msel = __ballot_sync(0xFFFFFFFFu, sel);
        int rank = __popc(msel & ((1u << lane) - 1));
        int basep = 0;
        if (lane == 0 && msel) basep = atomicAdd(&s_cnt, __popc(msel));
        basep = __shfl_sync(0xFFFFFFFFu, basep, 0);
        if (sel) {
            int pp = basep + rank;
            if (pp < 2048)
                cand[pp] = ((unsigned long long)cb[q] << 32) | (unsigned)(A_ - 1 - a);
        }
    }
    __syncthreads();
    int total = min(s_cnt, 2048);
    for (int t = total + tid; t < 2048; t += 1024) cand[t] = 0ull;
    __syncthreads();

    // hybrid bitonic sort, descending, unique keys
    unsigned long long vA = cand[tid], vB = cand[tid + 1024];
    #pragma unroll
    for (int k = 2; k <= 32; k <<= 1) {
        bool descA = ((tid & k) == 0);
        #pragma unroll
        for (int j = k >> 1; j > 0; j >>= 1) {
            bool up = ((tid & j) == 0);
            bool takeMax = (up == descA);
            unsigned long long oA = __shfl_xor_sync(0xFFFFFFFFu, vA, j);
            vA = takeMax ? (vA > oA ? vA : oA) : (vA < oA ? vA : oA);
            unsigned long long oB = __shfl_xor_sync(0xFFFFFFFFu, vB, j);
            vB = takeMax ? (vB > oB ? vB : oB) : (vB < oB ? vB : oB);
        }
    }
    cand[tid] = vA; cand[tid + 1024] = vB;

    #pragma unroll
    for (int k = 64; k <= 2048; k <<= 1) {
        for (int j = k >> 1; j >= 32; j >>= 1) {
            __syncthreads();
            #pragma unroll
            for (int tt = 0; tt < 2; tt++) {
                int t = tid + tt * 1024;
                int ixj = t ^ j;
                if (ixj > t) {
                    unsigned long long x = cand[t], y = cand[ixj];
                    bool desc = ((t & k) == 0);
                    if (desc ? (x < y) : (x > y)) { cand[t] = y; cand[ixj] = x; }
                }
            }
        }
        __syncthreads();
        vA = cand[tid]; vB = cand[tid + 1024];
        bool descA = ((tid & k) == 0);
        bool descB = (((tid + 1024) & k) == 0);
        #pragma unroll
        for (int j = 16; j > 0; j >>= 1) {
            bool up = ((tid & j) == 0);
            unsigned long long oA = __shfl_xor_sync(0xFFFFFFFFu, vA, j);
            vA = ((up == descA)) ? (vA > oA ? vA : oA) : (vA < oA ? vA : oA);
            unsigned long long oB = __shfl_xor_sync(0xFFFFFFFFu, vB, j);
            vB = ((up == descB)) ? (vB > oB ? vB : oB) : (vB < oB ? vB : oB);
        }
        cand[tid] = vA; cand[tid + 1024] = vB;
    }
    __syncthreads();

    {
        unsigned long long key = cand[tid];
        unsigned vbits = (unsigned)(key >> 32);
        int a = A_ - 1 - (int)(key & 0xFFFFFFFFull);
        int gi = b * A_ + a;
        float4 bx = g_box[gi];
        int cl = g_cls[gi];
        float sh = (float)cl * 7680.0f;
        float4 sb = make_float4(bx.x + sh, bx.y + sh, bx.z + sh, bx.w + sh);
        int oi = b * K_ + tid;
        g_tk_conf[oi]  = __uint_as_float(vbits);
        g_tk_box [oi]  = bx;
        g_tk_sarea[oi] = __fmul_rn(sb.z - sb.x, sb.w - sb.y);
        g_tk_cls [oi]  = cl;
    }
}

// ---------------- K3: fused on-the-fly NMS mask + sparse resolve + matching ----------------
__global__ void __launch_bounds__(1024) k_scan_match(
        const float* __restrict__ gt_boxes, const int* __restrict__ gt_cls,
        const void* __restrict__ gt_mask, const int* __restrict__ cat_to_super,
        float* __restrict__ out) {
    int b = blockIdx.x, tid = threadIdx.x, lane = tid & 31, wid = tid >> 5;
    __shared__ float4 sbx[K_];                 // unshifted boxes
    __shared__ float  sconf[K_];
    __shared__ float  sar[K_];                 // shifted-box areas
    __shared__ unsigned char scl[K_];
    __shared__ unsigned long long cmask[NC_ * 16];
    __shared__ unsigned long long keepw[16], validw[16];
    __shared__ unsigned long long colw[64];
    __shared__ unsigned int swords[32], pwords[32];
    __shared__ unsigned int vb[32];
    __shared__ int s_mode, s_done, s_budget;
    __shared__ float4 sgt[G_];
    __shared__ int sgc[G_], sgm[G_];
    __shared__ unsigned long long gkey[G_];
    __shared__ int ccnt[NC_];
    __shared__ unsigned short clist[NC_ * CLCAP_];
    __shared__ int scat[NC_], ssup[NSUP_];

    int oi = b * K_ + tid;
    float4 mybox = g_tk_box[oi];
    float  myconf = g_tk_conf[oi];
    int    mycls = g_tk_cls[oi];
    sbx[tid] = mybox; sconf[tid] = myconf;
    sar[tid] = g_tk_sarea[oi];
    scl[tid] = (unsigned char)mycls;

    if (tid == 0) { s_mode = 0; s_done = 0; s_budget = MAXDET_; }
    if (tid < 16) keepw[tid] = 0ull;
    if (tid < NC_) { ccnt[tid] = 0; scat[tid] = 0; }
    if (tid < NSUP_) ssup[tid] = 0;
    for (int t = tid; t < NC_ * 16; t += 1024) cmask[t] = 0ull;
    __syncthreads();
    atomicOr(&cmask[mycls * 16 + (tid >> 6)], 1ull << (tid & 63));

    // sniff gt_mask dtype from its first 1024 bytes (total elems = 32*32 = 1024)
    {
        const unsigned char* mu = (const unsigned char*)gt_mask;
        unsigned char v = mu[tid];
        if (v == 0x3F) atomicOr(&s_mode, 2);
        else if (v && (tid & 3)) atomicOr(&s_mode, 1);
    }
    unsigned bal = __ballot_sync(0xFFFFFFFFu, myconf > 0.0f);
    if (lane == 0) vb[wid] = bal;
    __syncthreads();

    if (tid < 16)
        validw[tid] = (unsigned long long)vb[2 * tid] | ((unsigned long long)vb[2 * tid + 1] << 32);
    int mode = s_mode;
    if (tid < G_) {
        const float4* gb4 = (const float4*)gt_boxes;
        sgt[tid] = gb4[b * G_ + tid];
        sgc[tid] = gt_cls[b * G_ + tid];
        int m;
        if (mode >= 2)      m = (((const float*)gt_mask)[b * G_ + tid] != 0.0f);
        else if (mode == 1) m = (((const unsigned char*)gt_mask)[b * G_ + tid] != 0);
        else                m = (((const int*)gt_mask)[b * G_ + tid] != 0);
        sgm[tid] = m;
    }
    __syncthreads();

    // greedy NMS: masks computed on the fly vs kept same-class columns,
    // sparse serial resolve, MAX_DET cap fused (early exit at 300 kept).
    {
        int r = tid >> 4, w = tid & 15;   // warp wid covers rows 2*wid, 2*wid+1
        for (int c = 0; c < 16; c++) {
            int i = c * 64 + r;
            int ci = scl[i];
            float shv = (float)ci * 7680.0f;
            float4 bi = sbx[i];
            float bix = bi.x + shv, biy = bi.y + shv;
            float biz = bi.z + shv, biw = bi.w + shv;
            float ai = sar[i];
            bool s = false;
            unsigned long long word = 0ull;
            if (w < c) {
                // suppressed by any KEPT same-class column in chunk w?
                unsigned long long m = cmask[ci * 16 + w] & keepw[w];
                int j0 = w * 64;
                while (m) {
                    int t2 = __ffsll(m) - 1; m &= m - 1;
                    float4 bj = sbx[j0 + t2];
                    float jx = bj.x + shv, jy = bj.y + shv;
                    float jz = bj.z + shv, jw2 = bj.w + shv;
                    float lx = fmaxf(bix, jx), ly = fmaxf(biy, jy);
                    float rx = fminf(biz, jz), ry = fminf(biw, jw2);
                    float ww = fmaxf(rx - lx, 0.0f), hh = fmaxf(ry - ly, 0.0f);
                    float inter = __fmul_rn(ww, hh);
                    float den = ai + sar[j0 + t2];
                    den = den - inter;
                    den = den + 1e-9f;
                    float q = inter / den;
                    if (q > 0.45f) { s = true; break; }
                }
            } else if (w == c) {
                // diagonal word: IoU bits vs same-class columns of own chunk
                unsigned long long m = cmask[ci * 16 + c];
                int j0 = c * 64;
                while (m) {
                    int t2 = __ffsll(m) - 1; m &= m - 1;
                    float4 bj = sbx[j0 + t2];
                    float jx = bj.x + shv, jy = bj.y + shv;
                    float jz = bj.z + shv, jw2 = bj.w + shv;
                    float lx = fmaxf(bix, jx), ly = fmaxf(biy, jy);
                    float rx = fminf(biz, jz), ry = fminf(biw, jw2);
                    float ww = fmaxf(rx - lx, 0.0f), hh = fmaxf(ry - ly, 0.0f);
                    float inter = __fmul_rn(ww, hh);
                    float den = ai + sar[j0 + t2];
                    den = den - inter;
                    den = den + 1e-9f;
                    float q = inter / den;
                    if (q > 0.45f) word |= (1ull << t2);
                }
                colw[r] = word;
            }
            unsigned long long below_r = (r == 0) ? 0ull : ((1ull << r) - 1ull);
            bool probbit = (w == c) && ((word & below_r) != 0ull);
            unsigned sb2 = __ballot_sync(0xFFFFFFFFu, s);
            unsigned pb2 = __ballot_sync(0xFFFFFFFFu, probbit);
            if (lane == 0) { swords[wid] = sb2; pwords[wid] = pb2; }
            __syncthreads();
            if (tid == 0) {
                unsigned long long sup = 0ull, prob = 0ull;
                #pragma unroll
                for (int q2 = 0; q2 < 32; q2++) {
                    unsigned bs_ = swords[q2], bp_ = pwords[q2];
                    if (bs_ & 0xFFFFu)      sup  |= 1ull << (2 * q2);
                    if (bs_ & 0xFFFF0000u)  sup  |= 1ull << (2 * q2 + 1);
                    if (bp_ & 0xFFFFu)      prob |= 1ull << (2 * q2);
                    if (bp_ & 0xFFFF0000u)  prob |= 1ull << (2 * q2 + 1);
                }
                unsigned long long base = validw[c] & ~sup;
                unsigned long long kw = base & ~prob;      // independent rows
                unsigned long long m = base & prob;        // serial fixup rows
                while (m) {
                    int r2 = __ffsll(m) - 1; m &= m - 1;
                    unsigned long long bel = (r2 == 0) ? 0ull : ((1ull << r2) - 1ull);
                    if (!(kw & colw[r2] & bel)) kw |= 1ull << r2;
                }
                int budget = s_budget;
                int pc = __popcll(kw);
                if (pc > budget) {
                    int rm = pc - budget;
                    for (int t3 = 0; t3 < rm; t3++)
                        kw &= ~(0x8000000000000000ull >> __clzll(kw));
                    pc = budget;
                }
                keepw[c] = kw;
                s_budget = budget - pc;
                if (budget == pc) s_done = 1;
            }
            __syncthreads();
            if (s_done) break;   // all later keep bits zeroed by cumsum<=300 cap
        }
    }

    bool kbit = ((keepw[tid >> 6] >> (tid & 63)) & 1ull) != 0;
    bool pv = kbit && (myconf > 0.5f);
    unsigned pb = __ballot_sync(0xFFFFFFFFu, pv);
    if (lane == 0) vb[wid] = pb;

    // compact matching candidates (pv preds) into per-class lists
    if (pv) {
        int p = atomicAdd(&ccnt[mycls], 1);
        if (p < CLCAP_) clist[mycls * CLCAP_ + p] = (unsigned short)tid;
    }
    // per-category / per-super GT counts
    if (tid < G_) {
        int c3 = sgc[tid];
        atomicAdd(&scat[c3], sgm[tid]);
        atomicAdd(&ssup[cat_to_super[c3]], sgm[tid]);
    }
    __syncthreads();

    // warp g handles gt g: only same-class pv preds are eligible
    {
        int g = wid;
        float4 gb = sgt[g];
        int gc = sgc[g];
        float ga = __fmul_rn(gb.z - gb.x, gb.w - gb.y);
        int n = min(ccnt[gc], CLCAP_);
        unsigned long long key = 0ull;
        for (int t = lane; t < n; t += 32) {
            int idx = clist[gc * CLCAP_ + t];
            float4 pbx = sbx[idx];
            float ap = __fmul_rn(pbx.z - pbx.x, pbx.w - pbx.y);
            float lx = fmaxf(pbx.x, gb.x), ly = fmaxf(pbx.y, gb.y);
            float rx = fminf(pbx.z, gb.z), ry = fminf(pbx.w, gb.w);
            float ww = fmaxf(rx - lx, 0.0f), hh = fmaxf(ry - ly, 0.0f);
            float inter = __fmul_rn(ww, hh);
            float den = ap + ga;
            den = den - inter;
            den = den + 1e-9f;
            float val = inter / den;
            unsigned fb = __float_as_uint(val);
            unsigned ord = fb ^ ((fb & 0x80000000u) ? 0xFFFFFFFFu : 0x80000000u);
            unsigned long long k2 = ((unsigned long long)ord << 32) | (unsigned)(K_ - 1 - idx);
            if (k2 > key) key = k2;
        }
        #pragma unroll
        for (int o = 16; o > 0; o >>= 1) {
            unsigned long long other = __shfl_xor_sync(0xFFFFFFFFu, key, o);
            if (other > key) key = other;
        }
        if (lane == 0) gkey[g] = key;
    }
    __syncthreads();

    if (tid == 0) {
        int n_pred = 0;
        for (int w2 = 0; w2 < 32; w2++) n_pred += __popc(vb[w2]);
        float sum_iou = 0.f, sum_conf = 0.f;
        int n_hit = 0, n_gt = 0;
        for (int g = 0; g < G_; g++) {
            int m = sgm[g];
            n_gt += m;
            unsigned long long key = gkey[g];
            unsigned ord = (unsigned)(key >> 32);
            unsigned fb = ord ^ ((ord & 0x80000000u) ? 0x80000000u : 0xFFFFFFFFu);
            float biou = __uint_as_float(fb);
            if (m && (biou > 0.6f)) {
                int idx = K_ - 1 - (int)(key & 0xFFFFFFFFull);
                n_hit++;
                sum_iou += biou;
                sum_conf += sconf[idx];
            }
        }
        float r0, r1, r2v, r3, r4;
        if (n_gt == 0) {
            if (n_pred == 0) { r0 = 1.f; r1 = 1.f; r2v = -1.f; r3 = -1.f; r4 = 1.f; }
            else             { r0 = 0.f; r1 = 1.f; r2v = -2.f; r3 = -2.f; r4 = 0.f; }
        } else {
            float fh = (float)n_hit;
            r0 = sum_iou / fmaxf(fh, 1.0f);
            r1 = (n_hit > 0) ? (sum_conf / fmaxf(fh, 1.0f)) : 1.0f;
            int bc2 = 0, bv = scat[0];
            for (int c3 = 1; c3 < NC_; c3++) if (scat[c3] > bv) { bv = scat[c3]; bc2 = c3; }
            int bs2 = 0, bvs = ssup[0];
            for (int s3 = 1; s3 < NSUP_; s3++) if (ssup[s3] > bvs) { bvs = ssup[s3]; bs2 = s3; }
            r2v = (float)bc2; r3 = (float)bs2;
            r4 = fh / fmaxf((float)n_gt, 1.0f);
        }
        out[b * 5 + 0] = r0; out[b * 5 + 1] = r1; out[b * 5 + 2] = r2v;
        out[b * 5 + 3] = r3; out[b * 5 + 4] = r4;
    }
}

// ---------------- launch ----------------
extern "C" void kernel_launch(void* const* d_in, const int* in_sizes, int n_in,
                              void* d_out, int out_size) {
    const float* preds = (const float*)d_in[0];
    const float* gtb   = (const float*)d_in[1];
    const int*   gtc   = (const int*)d_in[2];
    const void*  gtm   = d_in[3];
    const int*   c2s   = (const int*)d_in[4];
    float* out = (float*)d_out;

    int n1 = (B_ * A_ / 4 + 255) / 256;
    k_decode<<<n1, 256>>>(preds);
    k_topk<<<B_, 1024>>>();
    k_scan_match<<<B_, 1024>>>(gtb, gtc, gtm, c2s, out);
}